// round 6
// baseline (speedup 1.0000x reference)
#include <cuda_runtime.h>
#include <cstdint>

#define NT     384
#define ETILE  96
#define KDIM   256
#define HID    128
#define SROW   528                       // bytes per edge-row (256 fp16 + 16B pad)
#define ZBUF   (ETILE * SROW)            // 50688 B per buffer
#define OFF_PRT 0                        // 96 edges * 4 cgroups * 4B = 1536
#define OFF_Z   1536
#define SMEM_BYTES (OFF_Z + 2 * ZBUF)    // 102912 B -> 1 CTA/SM

// ---------------- helpers ----------------
__device__ __forceinline__ uint32_t smem_u32(const void* p) {
    uint32_t a;
    asm("{ .reg .u64 t; cvta.to.shared.u64 t, %1; cvt.u32.u64 %0, t; }" : "=r"(a) : "l"(p));
    return a;
}
__device__ __forceinline__ uint32_t hfpair(float lo, float hi) {
    uint32_t r;
    asm("cvt.rn.f16x2.f32 %0, %1, %2;" : "=r"(r) : "f"(hi), "f"(lo));
    return r;
}
__device__ __forceinline__ void ldmat4(uint32_t (&r)[4], uint32_t addr) {
    asm volatile("ldmatrix.sync.aligned.m8n8.x4.shared.b16 {%0,%1,%2,%3}, [%4];"
                 : "=r"(r[0]), "=r"(r[1]), "=r"(r[2]), "=r"(r[3]) : "r"(addr));
}
__device__ __forceinline__ void mma16816(float (&d)[4], const uint32_t (&a)[4],
                                         uint32_t b0, uint32_t b1) {
    asm volatile("mma.sync.aligned.m16n8k16.row.col.f32.f16.f16.f32 "
                 "{%0,%1,%2,%3}, {%4,%5,%6,%7}, {%8,%9}, {%0,%1,%2,%3};"
                 : "+f"(d[0]), "+f"(d[1]), "+f"(d[2]), "+f"(d[3])
                 : "r"(a[0]), "r"(a[1]), "r"(a[2]), "r"(a[3]), "r"(b0), "r"(b1));
}

// ---------------- gather: LDG -> fp16 cvt -> STS, streamed in 4 batches ----------------
// 384 threads cover 96 edges x 4 segments of 64 floats.
__device__ __forceinline__ void gather_tile(const float* __restrict__ zs,
                                            const float* __restrict__ zc,
                                            const int* __restrict__ row,
                                            const int* __restrict__ col,
                                            int base, int E, int tid, char* zbuf) {
    const int e = tid >> 2, seg = tid & 3;
    const int eg = base + e;
    const float* src;
    if (seg < 2) {
        int idx = (eg < E) ? row[eg] : 0;
        src = zs + (size_t)idx * HID + seg * 64;
    } else {
        int idx = (eg < E) ? col[eg] : 0;
        src = zc + (size_t)idx * HID + (seg - 2) * 64;
    }
    char* hb = zbuf + e * SROW + seg * 128;
    const float4* s4 = (const float4*)src;
    #pragma unroll
    for (int b = 0; b < 4; b++) {
        float4 v0 = s4[b * 4 + 0];
        float4 v1 = s4[b * 4 + 1];
        float4 v2 = s4[b * 4 + 2];
        float4 v3 = s4[b * 4 + 3];
        uint4 u0 = make_uint4(hfpair(v0.x, v0.y), hfpair(v0.z, v0.w),
                              hfpair(v1.x, v1.y), hfpair(v1.z, v1.w));
        uint4 u1 = make_uint4(hfpair(v2.x, v2.y), hfpair(v2.z, v2.w),
                              hfpair(v3.x, v3.y), hfpair(v3.z, v3.w));
        *(uint4*)(hb + b * 32)      = u0;
        *(uint4*)(hb + b * 32 + 16) = u1;
    }
}

// ---------------- kernel ----------------
__global__ void __launch_bounds__(NT, 1)
edge_decoder_mma(const float* __restrict__ zs, const float* __restrict__ zc,
                 const int* __restrict__ row, const int* __restrict__ col,
                 const float* __restrict__ W1, const float* __restrict__ b1,
                 const float* __restrict__ W2, const float* __restrict__ b2,
                 float* __restrict__ out, int E)
{
    extern __shared__ __align__(16) char sm[];
    float* prt = (float*)(sm + OFF_PRT);   // [96 edges][4 cgroups]
    char*  zsm = sm + OFF_Z;

    const int tid  = threadIdx.x;
    const int lane = tid & 31;
    const int wid  = tid >> 5;    // 0..11
    const int egrp = wid >> 2;    // 0..2: which 32-edge slice
    const int cgrp = wid & 3;     // 0..3: which 32-col slice
    const int tq   = lane & 3;
    const int tr   = lane >> 2;
    const int wcol = cgrp * 32;

    // ---- B = W1 fragments, fp16, register-resident (128 regs) ----
    uint32_t B[4][16][2];
    #pragma unroll
    for (int nb = 0; nb < 4; nb++) {
        const int n = wcol + nb * 8 + tr;
        #pragma unroll
        for (int s = 0; s < 16; s++) {
            #pragma unroll
            for (int hh = 0; hh < 2; hh++) {
                const int k0 = s * 16 + tq * 2 + hh * 8;
                B[nb][s][hh] = hfpair(W1[(size_t)k0 * HID + n],
                                      W1[(size_t)(k0 + 1) * HID + n]);
            }
        }
    }

    // ---- epilogue constants ----
    float b1v[4][2], w2v[4][2];
    #pragma unroll
    for (int nb = 0; nb < 4; nb++)
        #pragma unroll
        for (int j = 0; j < 2; j++) {
            int c = wcol + nb * 8 + tq * 2 + j;
            b1v[nb][j] = b1[c];
            w2v[nb][j] = W2[c];
        }
    const float b2v = b2[0];

    const uint32_t zb0 = smem_u32(zsm);
    const uint32_t lanebase = (uint32_t)(lane & 15) * SROW + (uint32_t)(lane >> 4) * 16
                            + (uint32_t)egrp * (32 * SROW);

    const int numTiles = (E + ETILE - 1) / ETILE;
    int t = blockIdx.x;
    int buf = 0;

    if (t < numTiles)
        gather_tile(zs, zc, row, col, t * ETILE, E, tid, zsm);

    while (t < numTiles) {
        const int tn = t + gridDim.x;
        __syncthreads();   // buf ready; prt from prev tile consumed

        // gather next tile into other buffer (overlaps with MMA via other warps)
        if (tn < numTiles)
            gather_tile(zs, zc, row, col, tn * ETILE, E, tid, zsm + (buf ^ 1) * ZBUF);

        // ---- MMA mainloop ----
        float D[2][4][4];
        #pragma unroll
        for (int mb = 0; mb < 2; mb++)
            #pragma unroll
            for (int nb = 0; nb < 4; nb++)
                #pragma unroll
                for (int i = 0; i < 4; i++) D[mb][nb][i] = 0.f;

        const uint32_t zb = zb0 + (uint32_t)buf * ZBUF;
        #pragma unroll
        for (int s = 0; s < 16; s++) {
            uint32_t A[2][4];
            #pragma unroll
            for (int mb = 0; mb < 2; mb++)
                ldmat4(A[mb], zb + lanebase + (uint32_t)mb * (16 * SROW) + (uint32_t)s * 32);
            #pragma unroll
            for (int mb = 0; mb < 2; mb++)
                #pragma unroll
                for (int nb = 0; nb < 4; nb++)
                    mma16816(D[mb][nb], A[mb], B[nb][s][0], B[nb][s][1]);
        }

        // ---- epilogue: bias + ReLU + W2, quad-reduce, stash partials ----
        #pragma unroll
        for (int mb = 0; mb < 2; mb++) {
            float s0 = 0.f, s1 = 0.f;
            #pragma unroll
            for (int nb = 0; nb < 4; nb++) {
                s0 += fmaxf(D[mb][nb][0] + b1v[nb][0], 0.f) * w2v[nb][0];
                s0 += fmaxf(D[mb][nb][1] + b1v[nb][1], 0.f) * w2v[nb][1];
                s1 += fmaxf(D[mb][nb][2] + b1v[nb][0], 0.f) * w2v[nb][0];
                s1 += fmaxf(D[mb][nb][3] + b1v[nb][1], 0.f) * w2v[nb][1];
            }
            s0 += __shfl_xor_sync(0xffffffffu, s0, 1);
            s0 += __shfl_xor_sync(0xffffffffu, s0, 2);
            s1 += __shfl_xor_sync(0xffffffffu, s1, 1);
            s1 += __shfl_xor_sync(0xffffffffu, s1, 2);
            if (tq == 0) {
                int ebase = egrp * 32 + mb * 16 + tr;
                prt[ebase * 4 + cgrp]       = s0;
                prt[(ebase + 8) * 4 + cgrp] = s1;
            }
        }
        __syncthreads();
        if (tid < ETILE) {
            float4 p = ((const float4*)prt)[tid];
            float o = p.x + p.y + p.z + p.w + b2v;
            int eg = t * ETILE + tid;
            if (eg < E) out[eg] = o;
        }

        t = tn;
        buf ^= 1;
    }
}

extern "C" void kernel_launch(void* const* d_in, const int* in_sizes, int n_in,
                              void* d_out, int out_size)
{
    const float* zs  = (const float*)d_in[0];
    const float* zc  = (const float*)d_in[1];
    const int*   row = (const int*)d_in[2];
    const int*   col = (const int*)d_in[3];
    const float* W1  = (const float*)d_in[4];
    const float* b1  = (const float*)d_in[5];
    const float* W2  = (const float*)d_in[6];
    const float* b2  = (const float*)d_in[7];
    float* out = (float*)d_out;
    const int E = in_sizes[2];

    static bool attr_set = false;  // idempotent, not a work guard
    if (!attr_set) {
        cudaFuncSetAttribute(edge_decoder_mma,
                             cudaFuncAttributeMaxDynamicSharedMemorySize, SMEM_BYTES);
        attr_set = true;
    }

    int sms = 148;
    cudaDeviceGetAttribute(&sms, cudaDevAttrMultiProcessorCount, 0);
    int numTiles = (E + ETILE - 1) / ETILE;
    int grid = sms < numTiles ? sms : numTiles;

    edge_decoder_mma<<<grid, NT, SMEM_BYTES>>>(zs, zc, row, col, W1, b1, W2, b2, out, E);
}

// round 7
// speedup vs baseline: 2.2749x; 2.2749x over previous
#include <cuda_runtime.h>
#include <cstdint>

#define NT     128
#define ETILE  32
#define HID    128
#define SROW   512                      // bytes per edge-row, 32 chunks of 16B, XOR-swizzled
#define ZBUF   (ETILE * SROW)           // 16384 B per buffer
#define OFF_PRT 0                       // 32 edges * 4 cgroups * 4B = 512
#define OFF_Z   512
#define SMEM_BYTES (OFF_Z + 2 * ZBUF)   // 33280 B -> 2 CTAs/SM, under 48KB default

#define NS_U 6400000                    // student table in uint32 (fp16 pairs)
#define NC_U 1280000
__device__ uint32_t g_zh[NS_U + NC_U];  // fp16 tables scratch (31 MB)

// ---------------- helpers ----------------
__device__ __forceinline__ uint32_t smem_u32(const void* p) {
    uint32_t a;
    asm("{ .reg .u64 t; cvta.to.shared.u64 t, %1; cvt.u32.u64 %0, t; }" : "=r"(a) : "l"(p));
    return a;
}
__device__ __forceinline__ uint32_t hfpair(float lo, float hi) {
    uint32_t r;
    asm("cvt.rn.f16x2.f32 %0, %1, %2;" : "=r"(r) : "f"(hi), "f"(lo));
    return r;
}
__device__ __forceinline__ void ldmat4(uint32_t (&r)[4], uint32_t addr) {
    asm volatile("ldmatrix.sync.aligned.m8n8.x4.shared.b16 {%0,%1,%2,%3}, [%4];"
                 : "=r"(r[0]), "=r"(r[1]), "=r"(r[2]), "=r"(r[3]) : "r"(addr));
}
__device__ __forceinline__ void mma16816(float (&d)[4], const uint32_t (&a)[4],
                                         uint32_t b0, uint32_t b1) {
    asm volatile("mma.sync.aligned.m16n8k16.row.col.f32.f16.f16.f32 "
                 "{%0,%1,%2,%3}, {%4,%5,%6,%7}, {%8,%9}, {%0,%1,%2,%3};"
                 : "+f"(d[0]), "+f"(d[1]), "+f"(d[2]), "+f"(d[3])
                 : "r"(a[0]), "r"(a[1]), "r"(a[2]), "r"(a[3]), "r"(b0), "r"(b1));
}

// ---------------- table convert: fp32 -> fp16 pairs (run each call) ----------------
__global__ void cvt_tables(const float* __restrict__ zs, const float* __restrict__ zc) {
    const int total = NS_U + NC_U;
    for (int i = blockIdx.x * blockDim.x + threadIdx.x; i < total;
         i += gridDim.x * blockDim.x) {
        const float* src = (i < NS_U) ? (zs + 2 * (size_t)i)
                                      : (zc + 2 * (size_t)(i - NS_U));
        g_zh[i] = hfpair(src[0], src[1]);
    }
}

// ---------------- gather: 8 threads/edge, coalesced fp16 chunks ----------------
// lane mapping inside warp: e_in_warp = lane>>3 (4 edges/warp), q = lane&7.
// Each thread holds chunks c = {q, 8+q, 16+q, 24+q} of its edge-row (student 0-15, course 16-31).
struct PV { uint4 v[4]; };

__device__ __forceinline__ void pref_load(const int* __restrict__ row,
                                          const int* __restrict__ col,
                                          int base, int E, int e_t, int q, PV& pv) {
    const int eg = base + e_t;
    const int ri = (eg < E) ? row[eg] : 0;
    const int ci = (eg < E) ? col[eg] : 0;
    const uint4* su = (const uint4*)(g_zh + (size_t)ri * 64);          // 16 chunks/row
    const uint4* cu = (const uint4*)(g_zh + NS_U + (size_t)ci * 64);
    pv.v[0] = su[q];
    pv.v[1] = su[8 + q];
    pv.v[2] = cu[q];
    pv.v[3] = cu[8 + q];
}
__device__ __forceinline__ void pref_store(char* zbuf, int e_t, int q, const PV& pv) {
    char* rowp = zbuf + e_t * SROW;
    #pragma unroll
    for (int j = 0; j < 4; j++) {
        int c  = 8 * j + q;
        int cs = (c & 24) | ((c ^ e_t) & 7);   // XOR swizzle -> conflict-free STS/LDSM
        *(uint4*)(rowp + cs * 16) = pv.v[j];
    }
}

// ---------------- kernel ----------------
__global__ void __launch_bounds__(NT, 2)
edge_decoder_mma(const int* __restrict__ row, const int* __restrict__ col,
                 const float* __restrict__ W1, const float* __restrict__ b1,
                 const float* __restrict__ W2, const float* __restrict__ b2,
                 float* __restrict__ out, int E)
{
    extern __shared__ __align__(16) char sm[];
    float* prt = (float*)(sm + OFF_PRT);   // [32 edges][4 cgroups]
    char*  zsm = sm + OFF_Z;

    const int tid  = threadIdx.x;
    const int lane = tid & 31;
    const int wid  = tid >> 5;    // cgroup 0..3
    const int tq   = lane & 3;
    const int tr   = lane >> 2;
    const int wcol = wid * 32;

    // gather-role identity: 4 edges per warp per pass, 2 passes
    const int ge0 = wid * 4 + (lane >> 3);
    const int gq  = lane & 7;

    // ---- B = W1 fragments, fp16, register-resident (128 regs) ----
    uint32_t B[4][16][2];
    #pragma unroll
    for (int nb = 0; nb < 4; nb++) {
        const int n = wcol + nb * 8 + tr;
        #pragma unroll
        for (int s = 0; s < 16; s++) {
            #pragma unroll
            for (int hh = 0; hh < 2; hh++) {
                const int k0 = s * 16 + tq * 2 + hh * 8;
                B[nb][s][hh] = hfpair(W1[(size_t)k0 * HID + n],
                                      W1[(size_t)(k0 + 1) * HID + n]);
            }
        }
    }

    // ---- epilogue constants ----
    float b1v[4][2], w2v[4][2];
    #pragma unroll
    for (int nb = 0; nb < 4; nb++)
        #pragma unroll
        for (int j = 0; j < 2; j++) {
            int c = wcol + nb * 8 + tq * 2 + j;
            b1v[nb][j] = b1[c];
            w2v[nb][j] = W2[c];
        }
    const float b2v = b2[0];

    const uint32_t zb0 = smem_u32(zsm);
    const int r0 = lane & 15;      // ldsm row within 16
    const int hh0 = lane >> 4;     // 0: k-lo 16B, 1: k-hi 16B

    const int numTiles = (E + ETILE - 1) / ETILE;
    int t = blockIdx.x;
    int buf = 0;
    PV pv0, pv1;

    if (t < numTiles) {
        pref_load(row, col, t * ETILE, E, ge0,      gq, pv0);
        pref_load(row, col, t * ETILE, E, ge0 + 16, gq, pv1);
        pref_store(zsm, ge0,      gq, pv0);
        pref_store(zsm, ge0 + 16, gq, pv1);
    }

    while (t < numTiles) {
        const int tn = t + gridDim.x;
        __syncthreads();   // buf ready; prt consumed

        // issue next tile's loads early -> hidden under MMA
        if (tn < numTiles) {
            pref_load(row, col, tn * ETILE, E, ge0,      gq, pv0);
            pref_load(row, col, tn * ETILE, E, ge0 + 16, gq, pv1);
        }

        // ---- MMA mainloop ----
        float D[2][4][4];
        #pragma unroll
        for (int mb = 0; mb < 2; mb++)
            #pragma unroll
            for (int nb = 0; nb < 4; nb++)
                #pragma unroll
                for (int i = 0; i < 4; i++) D[mb][nb][i] = 0.f;

        const uint32_t zb = zb0 + (uint32_t)buf * ZBUF;
        #pragma unroll
        for (int s = 0; s < 16; s++) {
            uint32_t A[2][4];
            #pragma unroll
            for (int mb = 0; mb < 2; mb++) {
                const int r  = r0 + mb * 16;
                const int c  = 2 * s + hh0;
                const int cs = (c & 24) | ((c ^ r) & 7);
                ldmat4(A[mb], zb + (uint32_t)(r * SROW + cs * 16));
            }
            #pragma unroll
            for (int mb = 0; mb < 2; mb++)
                #pragma unroll
                for (int nb = 0; nb < 4; nb++)
                    mma16816(D[mb][nb], A[mb], B[nb][s][0], B[nb][s][1]);
        }

        // store next tile into other buffer
        if (tn < numTiles) {
            pref_store(zsm + (buf ^ 1) * ZBUF, ge0,      gq, pv0);
            pref_store(zsm + (buf ^ 1) * ZBUF, ge0 + 16, gq, pv1);
        }

        // ---- epilogue: bias + ReLU + W2, quad-reduce, stash partials ----
        #pragma unroll
        for (int mb = 0; mb < 2; mb++) {
            float s0 = 0.f, s1 = 0.f;
            #pragma unroll
            for (int nb = 0; nb < 4; nb++) {
                s0 += fmaxf(D[mb][nb][0] + b1v[nb][0], 0.f) * w2v[nb][0];
                s0 += fmaxf(D[mb][nb][1] + b1v[nb][1], 0.f) * w2v[nb][1];
                s1 += fmaxf(D[mb][nb][2] + b1v[nb][0], 0.f) * w2v[nb][0];
                s1 += fmaxf(D[mb][nb][3] + b1v[nb][1], 0.f) * w2v[nb][1];
            }
            s0 += __shfl_xor_sync(0xffffffffu, s0, 1);
            s0 += __shfl_xor_sync(0xffffffffu, s0, 2);
            s1 += __shfl_xor_sync(0xffffffffu, s1, 1);
            s1 += __shfl_xor_sync(0xffffffffu, s1, 2);
            if (tq == 0) {
                int ebase = mb * 16 + tr;
                prt[ebase * 4 + wid]       = s0;
                prt[(ebase + 8) * 4 + wid] = s1;
            }
        }
        __syncthreads();
        if (tid < ETILE) {
            float4 p = ((const float4*)prt)[tid];
            float o = p.x + p.y + p.z + p.w + b2v;
            int eg = t * ETILE + tid;
            if (eg < E) out[eg] = o;
        }

        t = tn;
        buf ^= 1;
    }
}

extern "C" void kernel_launch(void* const* d_in, const int* in_sizes, int n_in,
                              void* d_out, int out_size)
{
    const float* zs  = (const float*)d_in[0];
    const float* zc  = (const float*)d_in[1];
    const int*   row = (const int*)d_in[2];
    const int*   col = (const int*)d_in[3];
    const float* W1  = (const float*)d_in[4];
    const float* b1  = (const float*)d_in[5];
    const float* W2  = (const float*)d_in[6];
    const float* b2  = (const float*)d_in[7];
    float* out = (float*)d_out;
    const int E = in_sizes[2];

    int sms = 148;
    cudaDeviceGetAttribute(&sms, cudaDevAttrMultiProcessorCount, 0);

    // 1) convert embedding tables to fp16 scratch (deterministic, every call)
    cvt_tables<<<4 * sms, 256>>>(zs, zc);

    // 2) main fused gather + MMA kernel
    int numTiles = (E + ETILE - 1) / ETILE;
    int grid = 2 * sms;
    if (grid > numTiles) grid = numTiles;
    edge_decoder_mma<<<grid, NT, SMEM_BYTES>>>(row, col, W1, b1, W2, b2, out, E);
}